// round 3
// baseline (speedup 1.0000x reference)
#include <cuda_runtime.h>

#define Hdim  100
#define Gdim  400
#define Kcat  200
#define T_IN  1000
#define T_TOT 1300
#define NB    4
#define NCTA  128
#define NTHR  416

// Pre-transposed weights, written once per launch by prologue kernel.
__device__ float g_W1T[Hdim*Gdim];   // W_hh1^T   [k][g], k<100
__device__ float g_W2T[Kcat*Gdim];   // [W_ih2; W_hh2]^T [k][g], k<200

__global__ void prep_weights(const float* __restrict__ W_hh1,
                             const float* __restrict__ W_ih2,
                             const float* __restrict__ W_hh2) {
    int i = blockIdx.x * blockDim.x + threadIdx.x;
    if (i < Hdim*Gdim) {                       // writes coalesced over i
        int k = i / Gdim, g = i % Gdim;
        g_W1T[i] = W_hh1[g*Hdim + k];
    }
    if (i < Kcat*Gdim) {
        int k = i / Gdim, g = i % Gdim;
        g_W2T[i] = (k < Hdim) ? W_ih2[g*Hdim + k]
                              : W_hh2[g*Hdim + (k - Hdim)];
    }
}

__device__ __forceinline__ float tanhfast(float x) {
    float y;
    asm("tanh.approx.f32 %0, %1;" : "=f"(y) : "f"(x));
    return y;
}
__device__ __forceinline__ float sigfast(float x) {
    return fmaf(0.5f, tanhfast(0.5f * x), 0.5f);
}

__global__ __launch_bounds__(NTHR)
void lstm2_kernel(const float* __restrict__ input,
                  const float* __restrict__ W_ih1,
                  const float* __restrict__ b_ih1,
                  const float* __restrict__ b_hh1,
                  const float* __restrict__ b_ih2,
                  const float* __restrict__ b_hh2,
                  const float* __restrict__ W_lin,
                  const float* __restrict__ b_lin,
                  float* __restrict__ out)
{
    extern __shared__ float sm[];
    float*  W1s    = sm;                       // [100*400]
    float4* hcat   = (float4*)(W1s + Hdim*Gdim);   // [200] (h1|h2) x 4 batches
    float4* gates  = hcat + Kcat;              // [400] x 4 batches
    float*  b1s    = (float*)(gates + Gdim);   // [400]
    float*  b2s    = b1s + Gdim;               // [400]
    float*  wi1s   = b2s + Gdim;               // [400]
    float*  wlin   = wi1s + Gdim;              // [100]
    float4* xin    = (float4*)(wlin + Hdim + 4);   // [1000] (t-major, 4 batches)
    float4* ysv    = xin + T_IN;               // [1]  autoregressive x
    // total floats: 40000 + 800 + 1600 + 1200 + 104 + 4000 + 4 = 47708

    const int tid = threadIdx.x;
    const int b0  = blockIdx.x * NB;

    // ---- one-time init ----
    for (int i = tid; i < Hdim*Gdim; i += NTHR) W1s[i] = g_W1T[i];
    for (int i = tid; i < Gdim; i += NTHR) {
        b1s[i]  = b_ih1[i] + b_hh1[i];
        b2s[i]  = b_ih2[i] + b_hh2[i];
        wi1s[i] = W_ih1[i];
    }
    for (int i = tid; i < NB*T_IN; i += NTHR) {       // xin[t][b]
        int t = i >> 2, b = i & 3;
        ((float*)xin)[i] = input[(b0 + b)*T_IN + t];
    }
    if (tid < Hdim) wlin[tid] = W_lin[tid];
    for (int i = tid; i < Kcat; i += NTHR) hcat[i] = make_float4(0.f,0.f,0.f,0.f);
    const float blin_r = __ldg(b_lin);
    __syncthreads();

    // persistent per-thread parameters
    const int g  = tid;                 // gate role (tid < 400)
    const int cj = tid >> 2;            // cell role: hidden index
    const int cb = tid & 3;             //            batch index
    float bb1 = 0.f, bb2 = 0.f, wi = 0.f;
    if (tid < Gdim) { bb1 = b1s[g]; bb2 = b2s[g]; wi = wi1s[g]; }
    float c1 = 0.f, c2 = 0.f;

    for (int t = 0; t < T_TOT; ++t) {
        // ---- Layer 1 gates: a[g][b] = x[b]*wi[g] + sum_k W1T[k][g]*h1[k][b] ----
        if (tid < Gdim) {
            const float4 x = (t < T_IN) ? xin[t] : *ysv;
            float4 a;
            a.x = fmaf(x.x, wi, bb1);
            a.y = fmaf(x.y, wi, bb1);
            a.z = fmaf(x.z, wi, bb1);
            a.w = fmaf(x.w, wi, bb1);
            const float* wp = W1s + g;
            #pragma unroll 20
            for (int k = 0; k < Hdim; ++k) {
                const float  w = wp[k*Gdim];      // 128B coalesced, conflict-free
                const float4 h = hcat[k];         // broadcast
                a.x = fmaf(w, h.x, a.x);
                a.y = fmaf(w, h.y, a.y);
                a.z = fmaf(w, h.z, a.z);
                a.w = fmaf(w, h.w, a.w);
            }
            gates[g] = a;
        }
        __syncthreads();

        // ---- Layer 1 cell update (c1 in registers) ----
        if (tid < Gdim) {
            const float* gp = (const float*)gates;
            const float vi = gp[(cj         )*4 + cb];
            const float vf = gp[(cj +   Hdim)*4 + cb];
            const float vg = gp[(cj + 2*Hdim)*4 + cb];
            const float vo = gp[(cj + 3*Hdim)*4 + cb];
            c1 = fmaf(sigfast(vf), c1, sigfast(vi) * tanhfast(vg));
            ((float*)hcat)[cj*4 + cb] = sigfast(vo) * tanhfast(c1);
        }
        __syncthreads();

        // ---- Layer 2 gates: one fused 200-deep dot over [h1|h2], W2 from L2 ----
        if (tid < Gdim) {
            float4 a;
            a.x = a.y = a.z = a.w = bb2;
            const float* wp = g_W2T + g;
            #pragma unroll 20
            for (int k = 0; k < Kcat; ++k) {
                const float  w = __ldg(wp + k*Gdim);  // coalesced, L2-resident
                const float4 h = hcat[k];
                a.x = fmaf(w, h.x, a.x);
                a.y = fmaf(w, h.y, a.y);
                a.z = fmaf(w, h.z, a.z);
                a.w = fmaf(w, h.w, a.w);
            }
            gates[g] = a;
        }
        __syncthreads();

        // ---- Layer 2 cell update ----
        if (tid < Gdim) {
            const float* gp = (const float*)gates;
            const float vi = gp[(cj         )*4 + cb];
            const float vf = gp[(cj +   Hdim)*4 + cb];
            const float vg = gp[(cj + 2*Hdim)*4 + cb];
            const float vo = gp[(cj + 3*Hdim)*4 + cb];
            c2 = fmaf(sigfast(vf), c2, sigfast(vi) * tanhfast(vg));
            ((float*)hcat)[(Hdim + cj)*4 + cb] = sigfast(vo) * tanhfast(c2);
        }
        __syncthreads();

        // ---- Output projection: y[b] = h2[b]·wlin + b_lin (one warp per batch) ----
        if (tid < 128) {
            const int w = tid >> 5, l = tid & 31;
            float s = 0.f;
            #pragma unroll
            for (int j = 0; j < Hdim; j += 32) {
                int jj = j + l;
                if (jj < Hdim)
                    s = fmaf(((const float*)hcat)[(Hdim + jj)*4 + w], wlin[jj], s);
            }
            #pragma unroll
            for (int o = 16; o > 0; o >>= 1)
                s += __shfl_down_sync(0xffffffffu, s, o);
            if (l == 0) {
                const float y = s + blin_r;
                out[(b0 + w)*T_TOT + t] = y;
                ((float*)ysv)[w] = y;
            }
        }
        __syncthreads();
    }
}

extern "C" void kernel_launch(void* const* d_in, const int* in_sizes, int n_in,
                              void* d_out, int out_size) {
    const float* input = (const float*)d_in[0];
    const float* W_ih1 = (const float*)d_in[1];
    const float* W_hh1 = (const float*)d_in[2];
    const float* b_ih1 = (const float*)d_in[3];
    const float* b_hh1 = (const float*)d_in[4];
    const float* W_ih2 = (const float*)d_in[5];
    const float* W_hh2 = (const float*)d_in[6];
    const float* b_ih2 = (const float*)d_in[7];
    const float* b_hh2 = (const float*)d_in[8];
    const float* W_lin = (const float*)d_in[9];
    const float* b_lin = (const float*)d_in[10];
    float* out = (float*)d_out;

    prep_weights<<<(Kcat*Gdim + 255)/256, 256>>>(W_hh1, W_ih2, W_hh2);

    const int smem_bytes = 47708 * (int)sizeof(float);
    cudaFuncSetAttribute(lstm2_kernel,
                         cudaFuncAttributeMaxDynamicSharedMemorySize, smem_bytes);
    lstm2_kernel<<<NCTA, NTHR, smem_bytes>>>(input, W_ih1, b_ih1, b_hh1,
                                             b_ih2, b_hh2, W_lin, b_lin, out);
}

// round 4
// speedup vs baseline: 2.8572x; 2.8572x over previous
#include <cuda_runtime.h>

#define Hdim  100
#define Gdim  400
#define T_IN  1000
#define T_TOT 1300
#define NB    4
#define NCTA  128
#define NTHR  800

// Pre-packed transposed weights: float2 over k-pairs, [k/2][g].
__device__ float2 g_W1P[50 * Gdim];    // W_hh1^T  k<100
__device__ float2 g_W2P[100 * Gdim];   // [W_ih2; W_hh2]^T  k<200

__global__ void prep_weights(const float* __restrict__ W_hh1,
                             const float* __restrict__ W_ih2,
                             const float* __restrict__ W_hh2) {
    int i = blockIdx.x * blockDim.x + threadIdx.x;
    if (i < 50 * Gdim) {
        int k2 = i / Gdim, g = i % Gdim, k = 2 * k2;
        g_W1P[i] = make_float2(W_hh1[g*Hdim + k], W_hh1[g*Hdim + k + 1]);
    } else if (i < 150 * Gdim) {
        int j = i - 50 * Gdim;
        int k2 = j / Gdim, g = j % Gdim, k = 2 * k2;
        g_W2P[j] = (k < Hdim)
            ? make_float2(W_ih2[g*Hdim + k],          W_ih2[g*Hdim + k + 1])
            : make_float2(W_hh2[g*Hdim + (k - Hdim)], W_hh2[g*Hdim + (k - Hdim) + 1]);
    }
}

typedef unsigned long long u64;

__device__ __forceinline__ u64 pack2(float v) {
    u64 r; asm("mov.b64 %0, {%1, %1};" : "=l"(r) : "f"(v)); return r;
}
__device__ __forceinline__ void fma2(u64& a, u64 w, u64 h) {
    asm("fma.rn.f32x2 %0, %1, %2, %0;" : "+l"(a) : "l"(w), "l"(h));
}
__device__ __forceinline__ float tanhfast(float x) {
    float y; asm("tanh.approx.f32 %0, %1;" : "=f"(y) : "f"(x)); return y;
}
__device__ __forceinline__ float sigfast(float x) {
    return fmaf(0.5f, tanhfast(0.5f * x), 0.5f);
}

__global__ __launch_bounds__(NTHR, 1)
void lstm2_kernel(const float* __restrict__ input,
                  const float* __restrict__ W_ih1,
                  const float* __restrict__ b_ih1,
                  const float* __restrict__ b_hh1,
                  const float* __restrict__ b_ih2,
                  const float* __restrict__ b_hh2,
                  const float* __restrict__ W_lin,
                  const float* __restrict__ b_lin,
                  float* __restrict__ out)
{
    extern __shared__ float sm[];
    float2*     W1s    = (float2*)sm;                    // [50*400]  W_hh1^T packed
    float4*     hcat   = (float4*)(sm + 40000);          // [200] (h1|h2) x 4 batches
    ulonglong2* gatesA = (ulonglong2*)(hcat + 200);      // [400] partial (half A)
    ulonglong2* gatesB = gatesA + Gdim;                  // [400] partial (half B)
    float4*     xin    = (float4*)(gatesB + Gdim);       // [1000] input, t-major
    float4*     ysv    = xin + T_IN;                     // [1]  autoregressive x
    float*      wlin   = (float*)(ysv + 1);              // [100]
    // floats: 40000 + 800 + 1600 + 1600 + 4000 + 4 + 100 = 48104 (192416 B)

    const int tid  = threadIdx.x;
    const int b0   = blockIdx.x * NB;
    const bool hA  = (tid < Gdim);
    const int  g   = hA ? tid : tid - Gdim;

    // ---- one-time init ----
    for (int i = tid; i < 50 * Gdim; i += NTHR) W1s[i] = g_W1P[i];
    for (int i = tid; i < NB * T_IN; i += NTHR) {        // xin[t][b]
        int t = i >> 2, b = i & 3;
        ((float*)xin)[i] = input[(b0 + b) * T_IN + t];
    }
    if (tid < Hdim) wlin[tid] = W_lin[tid];
    for (int i = tid; i < 200; i += NTHR) hcat[i] = make_float4(0.f, 0.f, 0.f, 0.f);
    const float blin_r = __ldg(b_lin);

    // per-thread constants (bias/x-weight only applied by half A)
    const u64 bb1p = hA ? pack2(b_ih1[g] + b_hh1[g]) : 0ull;
    const u64 bb2p = hA ? pack2(b_ih2[g] + b_hh2[g]) : 0ull;
    const u64 wip  = hA ? pack2(W_ih1[g]) : 0ull;
    const int k2L1 = hA ? 0 : 25;    // layer-1 k-pair range start (k: 0..49 / 50..99)
    const int k2L2 = hA ? 0 : 50;    // layer-2 k-pair range start (k: 0..99 / 100..199)

    const int cj = tid >> 2;         // cell role (tid < 400)
    const int cb = tid & 3;
    float c1 = 0.f, c2 = 0.f;
    __syncthreads();

    for (int t = 0; t < T_TOT; ++t) {
        // ---- Layer 1 gate partials ----
        {
            const ulonglong2 xp = (t < T_IN) ? *(const ulonglong2*)(xin + t)
                                             : *(const ulonglong2*)ysv;
            u64 a0 = bb1p, a1 = bb1p;
            if (hA) { fma2(a0, wip, xp.x); fma2(a1, wip, xp.y); }
            const float2* wp = W1s + g;
            #pragma unroll 5
            for (int k2 = k2L1; k2 < k2L1 + 25; ++k2) {
                const float2 w  = wp[k2 * Gdim];                          // 2 wf
                const u64 w0 = pack2(w.x), w1 = pack2(w.y);
                const ulonglong2 h0 = *(const ulonglong2*)(hcat + 2*k2);     // bcast
                const ulonglong2 h1 = *(const ulonglong2*)(hcat + 2*k2 + 1);
                fma2(a0, w0, h0.x); fma2(a1, w0, h0.y);
                fma2(a0, w1, h1.x); fma2(a1, w1, h1.y);
            }
            ulonglong2 r; r.x = a0; r.y = a1;
            if (hA) gatesA[g] = r; else gatesB[g] = r;
        }
        __syncthreads();

        // ---- Layer 1 cell update (c1 in registers) ----
        if (tid < Gdim) {
            const float* gA = (const float*)gatesA;
            const float* gB = (const float*)gatesB;
            const float vi = gA[(cj         )*4 + cb] + gB[(cj         )*4 + cb];
            const float vf = gA[(cj +   Hdim)*4 + cb] + gB[(cj +   Hdim)*4 + cb];
            const float vg = gA[(cj + 2*Hdim)*4 + cb] + gB[(cj + 2*Hdim)*4 + cb];
            const float vo = gA[(cj + 3*Hdim)*4 + cb] + gB[(cj + 3*Hdim)*4 + cb];
            c1 = fmaf(sigfast(vf), c1, sigfast(vi) * tanhfast(vg));
            ((float*)hcat)[cj*4 + cb] = sigfast(vo) * tanhfast(c1);
        }
        __syncthreads();

        // ---- Layer 2 gate partials: k-split 200-deep dot, weights from L2 ----
        {
            u64 a0 = bb2p, a1 = bb2p;
            const float2* wp = g_W2P + g;
            #pragma unroll 5
            for (int k2 = k2L2; k2 < k2L2 + 50; ++k2) {
                const float2 w  = __ldg(wp + k2 * Gdim);                  // LDG.64
                const u64 w0 = pack2(w.x), w1 = pack2(w.y);
                const ulonglong2 h0 = *(const ulonglong2*)(hcat + 2*k2);
                const ulonglong2 h1 = *(const ulonglong2*)(hcat + 2*k2 + 1);
                fma2(a0, w0, h0.x); fma2(a1, w0, h0.y);
                fma2(a0, w1, h1.x); fma2(a1, w1, h1.y);
            }
            ulonglong2 r; r.x = a0; r.y = a1;
            if (hA) gatesA[g] = r; else gatesB[g] = r;
        }
        __syncthreads();

        // ---- Layer 2 cell update ----
        if (tid < Gdim) {
            const float* gA = (const float*)gatesA;
            const float* gB = (const float*)gatesB;
            const float vi = gA[(cj         )*4 + cb] + gB[(cj         )*4 + cb];
            const float vf = gA[(cj +   Hdim)*4 + cb] + gB[(cj +   Hdim)*4 + cb];
            const float vg = gA[(cj + 2*Hdim)*4 + cb] + gB[(cj + 2*Hdim)*4 + cb];
            const float vo = gA[(cj + 3*Hdim)*4 + cb] + gB[(cj + 3*Hdim)*4 + cb];
            c2 = fmaf(sigfast(vf), c2, sigfast(vi) * tanhfast(vg));
            ((float*)hcat)[(Hdim + cj)*4 + cb] = sigfast(vo) * tanhfast(c2);
        }
        __syncthreads();

        // ---- Output projection: y[b] = h2[b]·wlin + b_lin (one warp/batch) ----
        if (tid < 128) {
            const int w = tid >> 5, l = tid & 31;
            float s = 0.f;
            #pragma unroll
            for (int j = 0; j < Hdim; j += 32) {
                const int jj = j + l;
                if (jj < Hdim)
                    s = fmaf(((const float*)hcat)[(Hdim + jj)*4 + w], wlin[jj], s);
            }
            #pragma unroll
            for (int o = 16; o > 0; o >>= 1)
                s += __shfl_down_sync(0xffffffffu, s, o);
            if (l == 0) {
                const float y = s + blin_r;
                out[(b0 + w) * T_TOT + t] = y;
                ((float*)ysv)[w] = y;
            }
        }
        __syncthreads();
    }
}

extern "C" void kernel_launch(void* const* d_in, const int* in_sizes, int n_in,
                              void* d_out, int out_size) {
    const float* input = (const float*)d_in[0];
    const float* W_ih1 = (const float*)d_in[1];
    const float* W_hh1 = (const float*)d_in[2];
    const float* b_ih1 = (const float*)d_in[3];
    const float* b_hh1 = (const float*)d_in[4];
    const float* W_ih2 = (const float*)d_in[5];
    const float* W_hh2 = (const float*)d_in[6];
    const float* b_ih2 = (const float*)d_in[7];
    const float* b_hh2 = (const float*)d_in[8];
    const float* W_lin = (const float*)d_in[9];
    const float* b_lin = (const float*)d_in[10];
    float* out = (float*)d_out;

    prep_weights<<<(150 * Gdim + 255) / 256, 256>>>(W_hh1, W_ih2, W_hh2);

    const int smem_bytes = 48104 * (int)sizeof(float);
    cudaFuncSetAttribute(lstm2_kernel,
                         cudaFuncAttributeMaxDynamicSharedMemorySize, smem_bytes);
    lstm2_kernel<<<NCTA, NTHR, smem_bytes>>>(input, W_ih1, b_ih1, b_hh1,
                                             b_ih2, b_hh2, W_lin, b_lin, out);
}